// round 17
// baseline (speedup 1.0000x reference)
#include <cuda_runtime.h>
#include <cuda_fp16.h>
#include <cstdint>

#define N_NODES 50000
#define N_EDGES 800000
#define D 96
#define NTOT 192
#define CAP 128            // bucket capacity per node; rows 512B-aligned

// TF32 GEMM tiling (frozen round-8/12 config)
#define GM_MB 64
#define NMB ((N_NODES + GM_MB - 1) / GM_MB)   // 782 M-tiles
#define GEMM_GRID 296                          // 2 CTAs/SM, persistent
#define XP 72
#define WP 200
#define GEMM_THREADS 256
#define GEMM_SMEM ((D * XP + D * WP) * 4)      // 104448 B

// Scratch (no allocations allowed)
__device__ __half g_h[(size_t)N_NODES * D];         // lin(x), fp16
__device__ int   g_cur[N_NODES];                     // ticket counter == in-degree
__device__ int   g_csr_src[(size_t)N_NODES * CAP];   // bucket CSR (25.6 MB)

// ---------------------------------------------------------------------------
__global__ void k_zero_cur() {
    int i = blockIdx.x * blockDim.x + threadIdx.x;
    if (i < N_NODES) g_cur[i] = 0;
}

// bucket fill: one atomic ticket + one store per edge.
__global__ void k_fill(const int* __restrict__ src, const int* __restrict__ dst) {
    int e = blockIdx.x * blockDim.x + threadIdx.x;
    if (e < N_EDGES) {
        int d = dst[e];
        int pos = atomicAdd(&g_cur[d], 1);
        if (pos < CAP) g_csr_src[(size_t)d * CAP + pos] = src[e];
    }
}

// ---------------------------------------------------------------------------
// Persistent TF32 GEMM (frozen R12 config): tile = x[64x96] @ [Wlin;Wroot]^T + b.
__device__ __forceinline__ uint32_t f2tf32(float f) {
    uint32_t u;
    asm("cvt.rna.tf32.f32 %0, %1;" : "=r"(u) : "f"(f));
    return u;
}

__device__ __forceinline__ void mma_tf32(float* c, uint32_t a0, uint32_t a1,
                                         uint32_t a2, uint32_t a3,
                                         uint32_t b0, uint32_t b1) {
    asm volatile(
        "mma.sync.aligned.m16n8k8.row.col.f32.tf32.tf32.f32 "
        "{%0,%1,%2,%3}, {%4,%5,%6,%7}, {%8,%9}, {%0,%1,%2,%3};"
        : "+f"(c[0]), "+f"(c[1]), "+f"(c[2]), "+f"(c[3])
        : "r"(a0), "r"(a1), "r"(a2), "r"(a3), "r"(b0), "r"(b1));
}

__global__ void __launch_bounds__(GEMM_THREADS)
k_gemm_tf32(const float* __restrict__ x,
            const float* __restrict__ Wlin, const float* __restrict__ Wroot,
            const float* __restrict__ b_lin, const float* __restrict__ b_root,
            float* __restrict__ out) {
    extern __shared__ uint32_t sm_u[];
    uint32_t* xs = sm_u;                 // [k][m] pitch XP
    uint32_t* ws = sm_u + D * XP;        // [k][n] pitch WP

    const int tid = threadIdx.x;

    for (int t = tid; t < NTOT * (D / 4); t += GEMM_THREADS) {
        int n = t % NTOT;
        int k4 = (t / NTOT) * 4;
        const float* Wp = (n < D) ? (Wlin + (size_t)n * D) : (Wroot + (size_t)(n - D) * D);
        float4 v = *reinterpret_cast<const float4*>(Wp + k4);
        ws[(k4 + 0) * WP + n] = f2tf32(v.x);
        ws[(k4 + 1) * WP + n] = f2tf32(v.y);
        ws[(k4 + 2) * WP + n] = f2tf32(v.z);
        ws[(k4 + 3) * WP + n] = f2tf32(v.w);
    }

    const int w = tid >> 5;
    const int lane = tid & 31;
    const int wm = w & 3;
    const int wn = w >> 2;       // 0: lin half -> g_h (fp16), 1: root -> out (fp32)
    const int lr = lane >> 2;
    const int lc = lane & 3;

    float bias0[12], bias1[12];
    {
        const float* bb = wn ? b_root : b_lin;
#pragma unroll
        for (int nt = 0; nt < 12; nt++) {
            bias0[nt] = bb[nt * 8 + 2 * lc];
            bias1[nt] = bb[nt * 8 + 2 * lc + 1];
        }
    }

    const uint32_t* wb = ws + lc * WP + wn * 96 + lr;

    for (int mb = blockIdx.x; mb < NMB; mb += gridDim.x) {
        const int mbase = mb * GM_MB;
        __syncthreads();

        for (int t = tid; t < GM_MB * (D / 4); t += GEMM_THREADS) {
            int m = t & (GM_MB - 1);
            int k4 = (t >> 6) * 4;
            int gm = mbase + m;
            float4 v = make_float4(0.f, 0.f, 0.f, 0.f);
            if (gm < N_NODES)
                v = *reinterpret_cast<const float4*>(x + (size_t)gm * D + k4);
            xs[(k4 + 0) * XP + m] = f2tf32(v.x);
            xs[(k4 + 1) * XP + m] = f2tf32(v.y);
            xs[(k4 + 2) * XP + m] = f2tf32(v.z);
            xs[(k4 + 3) * XP + m] = f2tf32(v.w);
        }
        __syncthreads();

        float acc[12][4];
#pragma unroll
        for (int nt = 0; nt < 12; nt++) {
            acc[nt][0] = bias0[nt]; acc[nt][1] = bias1[nt];
            acc[nt][2] = bias0[nt]; acc[nt][3] = bias1[nt];
        }

        const uint32_t* xa = xs + lc * XP + wm * 16 + lr;
#pragma unroll
        for (int ks = 0; ks < 12; ks++) {
            const uint32_t* xk = xa + ks * 8 * XP;
            uint32_t a0 = xk[0];
            uint32_t a1 = xk[8];
            uint32_t a2 = xk[4 * XP];
            uint32_t a3 = xk[4 * XP + 8];
            const uint32_t* bk = wb + ks * 8 * WP;
#pragma unroll
            for (int nt = 0; nt < 12; nt++) {
                uint32_t b0 = bk[nt * 8];
                uint32_t b1 = bk[nt * 8 + 4 * WP];
                mma_tf32(acc[nt], a0, a1, a2, a3, b0, b1);
            }
        }

        int gm0 = mbase + wm * 16 + lr;
        if (wn) {
#pragma unroll
            for (int nt = 0; nt < 12; nt++) {
                int col = nt * 8 + 2 * lc;
                if (gm0 < N_NODES)
                    *reinterpret_cast<float2*>(out + (size_t)gm0 * D + col) =
                        make_float2(acc[nt][0], acc[nt][1]);
                if (gm0 + 8 < N_NODES)
                    *reinterpret_cast<float2*>(out + (size_t)(gm0 + 8) * D + col) =
                        make_float2(acc[nt][2], acc[nt][3]);
            }
        } else {
#pragma unroll
            for (int nt = 0; nt < 12; nt++) {
                int col = nt * 8 + 2 * lc;
                if (gm0 < N_NODES)
                    *reinterpret_cast<__half2*>(g_h + (size_t)gm0 * D + col) =
                        __floats2half2_rn(acc[nt][0], acc[nt][1]);
                if (gm0 + 8 < N_NODES)
                    *reinterpret_cast<__half2*>(g_h + (size_t)(gm0 + 8) * D + col) =
                        __floats2half2_rn(acc[nt][2], acc[nt][3]);
            }
        }
    }
}

// ---------------------------------------------------------------------------
// aggregation v3: one warp per dst node.
// - dinv computed inline from g_cur (k_dinv kernel eliminated)
// - 4-edge unroll, indices via one int4 load -> 4 independent gather chains
// - lane owns cols {2l, 2l+1} (one __half2 load) and {64+l} (one __half load)
__global__ void __launch_bounds__(256)
k_agg(float* __restrict__ out) {
    int gw = (blockIdx.x * 256 + threadIdx.x) >> 5;
    int lane = threadIdx.x & 31;
    if (gw >= N_NODES) return;

    int cnt = g_cur[gw];
    float dn = rsqrtf(fmaxf((float)cnt, 1.0f));
    cnt = min(cnt, CAP);
    const int* row = g_csr_src + (size_t)gw * CAP;

    float a0 = 0.f, a1 = 0.f, a2 = 0.f;   // cols 2l, 2l+1, 64+l
    int p = 0;
    for (; p + 4 <= cnt; p += 4) {
        int4 s4 = *reinterpret_cast<const int4*>(row + p);
        float n0 = dn * rsqrtf(fmaxf((float)g_cur[s4.x], 1.0f));
        float n1 = dn * rsqrtf(fmaxf((float)g_cur[s4.y], 1.0f));
        float n2 = dn * rsqrtf(fmaxf((float)g_cur[s4.z], 1.0f));
        float n3 = dn * rsqrtf(fmaxf((float)g_cur[s4.w], 1.0f));
        const __half* h0 = g_h + (size_t)s4.x * D;
        const __half* h1 = g_h + (size_t)s4.y * D;
        const __half* h2 = g_h + (size_t)s4.z * D;
        const __half* h3 = g_h + (size_t)s4.w * D;
        __half2 p0 = reinterpret_cast<const __half2*>(h0)[lane];
        __half2 p1 = reinterpret_cast<const __half2*>(h1)[lane];
        __half2 p2 = reinterpret_cast<const __half2*>(h2)[lane];
        __half2 p3 = reinterpret_cast<const __half2*>(h3)[lane];
        float t0 = __half2float(h0[64 + lane]);
        float t1 = __half2float(h1[64 + lane]);
        float t2 = __half2float(h2[64 + lane]);
        float t3 = __half2float(h3[64 + lane]);
        float2 f0 = __half22float2(p0);
        float2 f1 = __half22float2(p1);
        float2 f2 = __half22float2(p2);
        float2 f3 = __half22float2(p3);
        a0 = fmaf(f0.x, n0, a0); a1 = fmaf(f0.y, n0, a1); a2 = fmaf(t0, n0, a2);
        a0 = fmaf(f1.x, n1, a0); a1 = fmaf(f1.y, n1, a1); a2 = fmaf(t1, n1, a2);
        a0 = fmaf(f2.x, n2, a0); a1 = fmaf(f2.y, n2, a1); a2 = fmaf(t2, n2, a2);
        a0 = fmaf(f3.x, n3, a0); a1 = fmaf(f3.y, n3, a1); a2 = fmaf(t3, n3, a2);
    }
    for (; p < cnt; p++) {
        int s = row[p];
        float nn = dn * rsqrtf(fmaxf((float)g_cur[s], 1.0f));
        const __half* h = g_h + (size_t)s * D;
        float2 f = __half22float2(reinterpret_cast<const __half2*>(h)[lane]);
        float t = __half2float(h[64 + lane]);
        a0 = fmaf(f.x, nn, a0);
        a1 = fmaf(f.y, nn, a1);
        a2 = fmaf(t, nn, a2);
    }

    float* o = out + (size_t)gw * D;
    float2 r = *reinterpret_cast<float2*>(o + 2 * lane);
    float r2 = o[64 + lane];
    *reinterpret_cast<float2*>(o + 2 * lane) =
        make_float2(fmaxf(a0 + r.x, 0.f), fmaxf(a1 + r.y, 0.f));
    o[64 + lane] = fmaxf(a2 + r2, 0.f);
}

// ---------------------------------------------------------------------------
extern "C" void kernel_launch(void* const* d_in, const int* in_sizes, int n_in,
                              void* d_out, int out_size) {
    const float* x     = (const float*)d_in[0];
    const int*   edges = (const int*)d_in[1];
    const float* Wlin  = (const float*)d_in[2];
    const float* blin  = (const float*)d_in[3];
    const float* Wroot = (const float*)d_in[4];
    const float* broot = (const float*)d_in[5];
    float* out = (float*)d_out;

    const int* src = edges;            // edge_index[0, :]
    const int* dst = edges + N_EDGES;  // edge_index[1, :]

    static cudaStream_t s2 = []() {
        cudaStream_t s; cudaStreamCreateWithFlags(&s, cudaStreamNonBlocking); return s;
    }();
    static cudaEvent_t ev_fork = []() {
        cudaEvent_t e; cudaEventCreateWithFlags(&e, cudaEventDisableTiming); return e;
    }();
    static cudaEvent_t ev_gemm = []() {
        cudaEvent_t e; cudaEventCreateWithFlags(&e, cudaEventDisableTiming); return e;
    }();
    static bool cfg = []() {
        cudaFuncSetAttribute(k_gemm_tf32,
                             cudaFuncAttributeMaxDynamicSharedMemorySize, GEMM_SMEM);
        return true;
    }();
    (void)cfg;

    // fork FIRST: GEMM dependency-free from t=0 on s2
    cudaEventRecord(ev_fork, 0);
    cudaStreamWaitEvent(s2, ev_fork, 0);

    // CSR branch (submissions 1-2): zero -> bucket fill
    k_zero_cur<<<(N_NODES + 255) / 256, 256>>>();
    k_fill<<<(N_EDGES + 255) / 256, 256>>>(src, dst);

    // GEMM = submission #3, overlapped from t=0
    k_gemm_tf32<<<GEMM_GRID, GEMM_THREADS, GEMM_SMEM, s2>>>(
        x, Wlin, Wroot, blin, broot, out);
    cudaEventRecord(ev_gemm, s2);

    // join; agg = submission #4 -> ncu profiles agg this round
    cudaStreamWaitEvent(0, ev_gemm, 0);
    k_agg<<<(N_NODES * 32 + 255) / 256, 256>>>(out);
}